// round 2
// baseline (speedup 1.0000x reference)
#include <cuda_runtime.h>
#include <cstdint>
#include <cstddef>

#define NB    16
#define CC    192
#define HH    56
#define WW    56
#define HWP   (HH*WW)          // 3136
#define NPIX  (NB*HWP)         // 50176
#define HEADS 6
#define CHN   32
#define KT    486              // 81 * 6
#define SCALE 0.17677669529663689f   // 32^-0.5

// ---------------- scratch (device globals; no runtime allocation) -------------
__device__ float g_v  [NB*CC*HWP];                  // value projection   (38.5 MB)
__device__ float g_att[(size_t)NB*HWP*KT];          // softmaxed attention (97.5 MB)
__device__ float g_fold[NB*CC*HWP];                 // folded result      (38.5 MB)

// ---------------- packed f32x2 helpers ---------------------------------------
#define FMA2(acc,a,b) asm("fma.rn.f32x2 %0, %1, %2, %0;" : "+l"(acc) : "l"(a), "l"(b))

__device__ __forceinline__ unsigned long long pack2(float x, float y) {
    unsigned long long r;
    asm("mov.b64 %0, {%1, %2};" : "=l"(r) : "r"(__float_as_uint(x)), "r"(__float_as_uint(y)));
    return r;
}
__device__ __forceinline__ void unpack2(unsigned long long v, float& x, float& y) {
    unsigned int lo, hi;
    asm("mov.b64 {%0, %1}, %2;" : "=r"(lo), "=r"(hi) : "l"(v));
    x = __uint_as_float(lo); y = __uint_as_float(hi);
}

// ============================================================================
// Kernel A/D: 192x192 pointwise GEMM, register-tiled.
//   Out[n,d,hw] = sum_c X[n,c,hw] * Wm[c,d] (+ bias[d])
// 384 threads: thread = (dg in [0,48), pg in [0,8)), tid = dg*8+pg.
// Thread tile: 4 channels x 16 contiguous pixels (8 f32x2 pairs) = 32 accs.
// Block tile: 128 flattened pixels x 192 channels. W resident in smem,
// x staged in 64-deep K-chunks. Per c-step: 1 LDS.128 (w, ~broadcast) +
// 4 LDS.128 (x) + 32 FMA2 -> fma-pipe bound. Grid-stride, W loaded once.
// ============================================================================
#define GEMM_SMEM_BYTES ((192*192 + 64*128)*4)   // 180224

__global__ void __launch_bounds__(384, 1) gemm192_kernel(
    const float* __restrict__ X, const float* __restrict__ Wm,
    const float* __restrict__ bias, float* __restrict__ Out, int nTiles)
{
    extern __shared__ float sm[];
    float* wsm = sm;               // [192][192], row c contiguous in d
    float* xsm = sm + 192*192;     // [64][128]
    const int tid = threadIdx.x;
    const int dg  = tid >> 3;      // 0..47  -> d in [4dg, 4dg+4)
    const int pg  = tid & 7;       // 0..7   -> px in [16pg, 16pg+16)

    for (int i = tid; i < 192*192; i += 384) wsm[i] = Wm[i];

    unsigned long long b2[4];
    #pragma unroll
    for (int di = 0; di < 4; di++) {
        float b = bias ? bias[4*dg + di] : 0.0f;
        b2[di] = pack2(b, b);
    }

    for (int t = blockIdx.x; t < nTiles; t += gridDim.x) {
        const int g0 = t * 128;    // flattened pixel base
        unsigned long long acc[4][8];
        #pragma unroll
        for (int di = 0; di < 4; di++)
            #pragma unroll
            for (int pp = 0; pp < 8; pp++) acc[di][pp] = b2[di];

        for (int kc = 0; kc < 3; kc++) {
            __syncthreads();
            for (int i = tid; i < 64*128; i += 384) {
                int c = i >> 7, px = i & 127;
                int g = g0 + px;
                int n = g / HWP, hw = g - n*HWP;
                xsm[i] = X[((size_t)(n*CC) + kc*64 + c)*HWP + hw];
            }
            __syncthreads();

            #pragma unroll 1
            for (int r = 0; r < 64; r++) {
                const int c = kc*64 + r;
                float4 w4 = *(const float4*)(wsm + c*192 + 4*dg);
                unsigned long long w2[4];
                w2[0] = pack2(w4.x, w4.x); w2[1] = pack2(w4.y, w4.y);
                w2[2] = pack2(w4.z, w4.z); w2[3] = pack2(w4.w, w4.w);
                const ulonglong2* xr = (const ulonglong2*)(xsm + r*128 + 16*pg);
                ulonglong2 xv0 = xr[0], xv1 = xr[1], xv2 = xr[2], xv3 = xr[3];
                unsigned long long xs[8] = {xv0.x, xv0.y, xv1.x, xv1.y,
                                            xv2.x, xv2.y, xv3.x, xv3.y};
                #pragma unroll
                for (int di = 0; di < 4; di++)
                    #pragma unroll
                    for (int pp = 0; pp < 8; pp++)
                        FMA2(acc[di][pp], xs[pp], w2[di]);
            }
        }

        // direct stores: 16B per (thread, d, 4px group); groups never straddle
        // an image boundary (HWP % 4 == 0, groups 4-aligned).
        #pragma unroll
        for (int s = 0; s < 4; s++) {
            int g = g0 + 16*pg + 4*s;
            int n = g / HWP, hw = g - n*HWP;
            #pragma unroll
            for (int di = 0; di < 4; di++) {
                ulonglong2 uv;
                uv.x = acc[di][2*s]; uv.y = acc[di][2*s+1];
                *(ulonglong2*)(Out + ((size_t)(n*CC) + 4*dg + di)*HWP + hw) = uv;
            }
        }
    }
}

// ============================================================================
// Kernel B: attention logits GEMM + fused softmax, register-tiled.
// 432 threads: thread = (cg in [0,54), pg in [0,8)), tid = cg*8+pg.
// Thread tile: 9 att columns (= ONE (head,kout) softmax group!) x 8 pixels
// (4 f32x2 pairs) = 36 accs. Block tile: 64 pixels x 486 columns.
// Wa staged in 48-row smem chunks; softmax fully in registers.
// ============================================================================
#define ATT_SMEM_BYTES ((192*64 + 48*KT)*4)      // 142464

__global__ void __launch_bounds__(432, 1) att_kernel(
    const float* __restrict__ X, const float* __restrict__ Wa,
    const float* __restrict__ ba, float* __restrict__ Att)
{
    extern __shared__ float sm[];
    float* xsm = sm;               // [192][64]
    float* wsm = sm + 192*64;      // [48][486]
    const int tid = threadIdx.x;
    const int cg  = tid >> 3;      // 0..53 -> cols [9cg, 9cg+9)
    const int pg  = tid & 7;       // 0..7  -> px  [8pg, 8pg+8)
    const int t   = blockIdx.x;
    const int n   = t / 49;
    const int hw0 = (t - n*49) * 64;

    for (int i = tid; i < 192*64; i += 432) {
        int c = i >> 6, px = i & 63;
        xsm[i] = X[((size_t)(n*CC) + c)*HWP + hw0 + px];
    }

    unsigned long long acc[9][4];
    #pragma unroll
    for (int u = 0; u < 9; u++) {
        float b = ba[9*cg + u];
        unsigned long long b2 = pack2(b, b);
        #pragma unroll
        for (int pp = 0; pp < 4; pp++) acc[u][pp] = b2;
    }

    for (int kc = 0; kc < 4; kc++) {
        __syncthreads();
        for (int i = tid; i < 48*KT; i += 432) {
            int r = i / KT, col = i - r*KT;
            wsm[i] = Wa[(size_t)(48*kc + r)*KT + col];
        }
        __syncthreads();

        #pragma unroll 1
        for (int r = 0; r < 48; r++) {
            const float* wrow = wsm + r*KT + 9*cg;
            unsigned long long w2[9];
            #pragma unroll
            for (int u = 0; u < 9; u++) { float w = wrow[u]; w2[u] = pack2(w, w); }
            const ulonglong2* xr = (const ulonglong2*)(xsm + (48*kc + r)*64 + 8*pg);
            ulonglong2 xv0 = xr[0], xv1 = xr[1];
            unsigned long long xs[4] = {xv0.x, xv0.y, xv1.x, xv1.y};
            #pragma unroll
            for (int u = 0; u < 9; u++)
                #pragma unroll
                for (int pp = 0; pp < 4; pp++)
                    FMA2(acc[u][pp], xs[pp], w2[u]);
        }
    }

    // softmax over the 9 cols (one (head,kout) group) per pixel, in registers
    #pragma unroll
    for (int pp = 0; pp < 4; pp++) {
        float z0[9], z1[9];
        #pragma unroll
        for (int u = 0; u < 9; u++) unpack2(acc[u][pp], z0[u], z1[u]);
        #pragma unroll
        for (int half = 0; half < 2; half++) {
            float* z = half ? z1 : z0;
            float m = z[0];
            #pragma unroll
            for (int u = 1; u < 9; u++) m = fmaxf(m, z[u]);
            float e[9], s = 0.0f;
            #pragma unroll
            for (int u = 0; u < 9; u++) { e[u] = __expf((z[u]-m)*SCALE); s += e[u]; }
            float inv = 1.0f / s;
            int px = 8*pg + 2*pp + half;
            float* dst = Att + ((size_t)(n*HWP) + hw0 + px)*KT + 9*cg;
            #pragma unroll
            for (int u = 0; u < 9; u++) dst[u] = e[u]*inv;
        }
    }
}

// ============================================================================
// Kernel C: aggregation + fold (gather formulation, race-free).
// 384 threads = 6 heads x 64 pixels (8x8 tile); each thread loads its 81
// attention weights once, reuses over 32 channels from the smem v-window.
// ============================================================================
#define AGG_SMEM_BYTES ((192*145 + 192*64)*4)    // 160512

__global__ void __launch_bounds__(384, 1) agg_kernel(
    const float* __restrict__ V, const float* __restrict__ Att,
    float* __restrict__ Fold)
{
    extern __shared__ float sm[];
    float* vsm = sm;               // [192][145] (pos = ly*12+lx, 144 used)
    float* fsm = sm + 192*145;     // [192][64]
    const int tid = threadIdx.x;
    const int blk = blockIdx.x;
    const int n  = blk / 49;
    const int tt = blk - n*49;
    const int y0 = (tt / 7) * 8, x0 = (tt % 7) * 8;

    for (int i = tid; i < 192*144; i += 384) {
        int c = i / 144, pos = i - c*144;
        int ly = pos / 12, lx = pos - ly*12;
        int gy = y0 - 2 + ly, gx = x0 - 2 + lx;
        float val = 0.0f;
        if (gy >= 0 && gy < HH && gx >= 0 && gx < WW)
            val = V[((size_t)(n*CC) + c)*HWP + gy*WW + gx];
        vsm[c*145 + pos] = val;
    }
    __syncthreads();

    {
        const int head = tid >> 6;          // 0..5
        const int q    = tid & 63;
        const int qy = q >> 3, qx = q & 7;
        const int gy = y0 + qy, gx = x0 + qx;

        float w[81];
        #pragma unroll
        for (int i = 0; i < 3; i++)
        #pragma unroll
        for (int j = 0; j < 3; j++) {
            int py = gy + 1 - i, px = gx + 1 - j;
            if (py >= 0 && py < HH && px >= 0 && px < WW) {
                const float* ab = Att + ((size_t)n*HWP + py*WW + px)*KT
                                      + head*81 + (i*3+j)*9;
                #pragma unroll
                for (int u = 0; u < 9; u++) w[(i*3+j)*9+u] = ab[u];
            } else {
                #pragma unroll
                for (int u = 0; u < 9; u++) w[(i*3+j)*9+u] = 0.0f;
            }
        }

        #pragma unroll 1
        for (int ch = 0; ch < CHN; ch++) {
            const int cg = head*CHN + ch;
            const float* vb = vsm + cg*145;
            float vv[25];
            #pragma unroll
            for (int dy = 0; dy < 5; dy++)
            #pragma unroll
            for (int dx = 0; dx < 5; dx++)
                vv[dy*5+dx] = vb[(qy+dy)*12 + (qx+dx)];

            float p0=0.f, p1=0.f, p2=0.f, p3=0.f;
            #pragma unroll
            for (int i = 0; i < 3; i++)
            #pragma unroll
            for (int j = 0; j < 3; j++)
            #pragma unroll
            for (int a = 0; a < 3; a++)
            #pragma unroll
            for (int bb = 0; bb < 3; bb++) {
                const int widx = (i*3+j)*9 + a*3 + bb;
                float prod = w[widx] * vv[(a-i+2)*5 + (bb-j+2)];
                switch (widx & 3) { case 0: p0 += prod; break; case 1: p1 += prod; break;
                                    case 2: p2 += prod; break; default: p3 += prod; }
            }
            fsm[cg*64 + q] = (p0+p1) + (p2+p3);
        }
    }
    __syncthreads();

    for (int i = tid; i < 192*64; i += 384) {
        int c = i >> 6, q = i & 63;
        int qy = q >> 3, qx = q & 7;
        Fold[((size_t)(n*CC) + c)*HWP + (y0+qy)*WW + (x0+qx)] = fsm[i];
    }
}

// ============================================================================
// Launch
// ============================================================================
extern "C" void kernel_launch(void* const* d_in, const int* in_sizes, int n_in,
                              void* d_out, int out_size)
{
    const float* x  = (const float*)d_in[0];
    const float* Wv = (const float*)d_in[1];
    const float* Wa = (const float*)d_in[2];
    const float* ba = (const float*)d_in[3];
    const float* Wp = (const float*)d_in[4];
    const float* bp = (const float*)d_in[5];
    float* out = (float*)d_out;

    float *vp, *ap, *fp;
    cudaGetSymbolAddress((void**)&vp, g_v);
    cudaGetSymbolAddress((void**)&ap, g_att);
    cudaGetSymbolAddress((void**)&fp, g_fold);

    cudaFuncSetAttribute(gemm192_kernel, cudaFuncAttributeMaxDynamicSharedMemorySize, GEMM_SMEM_BYTES);
    cudaFuncSetAttribute(att_kernel,     cudaFuncAttributeMaxDynamicSharedMemorySize, ATT_SMEM_BYTES);
    cudaFuncSetAttribute(agg_kernel,     cudaFuncAttributeMaxDynamicSharedMemorySize, AGG_SMEM_BYTES);

    const int nTiles = NPIX / 128;                // 392 tiles of 128 pixels

    // value projection: v = x @ Wv
    gemm192_kernel<<<148, 384, GEMM_SMEM_BYTES>>>(x, Wv, nullptr, vp, nTiles);
    // attention logits + fused softmax
    att_kernel<<<NB*49, 432, ATT_SMEM_BYTES>>>(x, Wa, ba, ap);
    // aggregation + fold
    agg_kernel<<<NB*49, 384, AGG_SMEM_BYTES>>>(vp, ap, fp);
    // output projection: out = folded @ Wp + bp
    gemm192_kernel<<<148, 384, GEMM_SMEM_BYTES>>>(fp, Wp, bp, out, nTiles);
}

// round 3
// speedup vs baseline: 1.6562x; 1.6562x over previous
#include <cuda_runtime.h>
#include <cstdint>
#include <cstddef>

#define NB    16
#define CC    192
#define HH    56
#define WW    56
#define HWP   (HH*WW)          // 3136
#define NPIX  (NB*HWP)         // 50176
#define HEADS 6
#define CHN   32
#define KT    486              // 81 * 6
#define KTP   648              // padded: 54 groups * 12
#define SCALE 0.17677669529663689f   // 32^-0.5

// ---------------- scratch (device globals; no runtime allocation) -------------
__device__ float g_v   [NB*CC*HWP];                 // value projection    (38.5 MB)
__device__ float g_att [(size_t)NPIX*KTP];          // softmaxed att, padded (130 MB)
__device__ float g_fold[NB*CC*HWP];                 // folded result       (38.5 MB)
__device__ float g_wpad[CC*KTP];                    // padded Wa           (497 KB)

// ---------------- packed f32x2 helpers ---------------------------------------
#define FMA2(acc,a,b) asm("fma.rn.f32x2 %0, %1, %2, %0;" : "+l"(acc) : "l"(a), "l"(b))

__device__ __forceinline__ unsigned long long pack2(float x, float y) {
    unsigned long long r;
    asm("mov.b64 %0, {%1, %2};" : "=l"(r) : "r"(__float_as_uint(x)), "r"(__float_as_uint(y)));
    return r;
}
__device__ __forceinline__ void unpack2(unsigned long long v, float& x, float& y) {
    unsigned int lo, hi;
    asm("mov.b64 {%0, %1}, %2;" : "=r"(lo), "=r"(hi) : "l"(v));
    x = __uint_as_float(lo); y = __uint_as_float(hi);
}

// ============================================================================
// Wa pre-pad: [192][486] -> [192][648], group g's 9 cols at 12g..12g+8, pad 0.
// ============================================================================
__global__ void pad_wa_kernel(const float* __restrict__ Wa, float* __restrict__ Wp)
{
    int i = blockIdx.x * 256 + threadIdx.x;
    if (i >= CC*KTP) return;
    int c = i / KTP, col = i - c*KTP;
    int g = col / 12, u = col - g*12;
    Wp[i] = (u < 9) ? Wa[c*KT + g*9 + u] : 0.0f;
}

// ============================================================================
// Kernel A/D: 192x192 pointwise GEMM, SIMT outer-product tiling.
//   Out[n,d,hw] = sum_c X[n,c,hw] * Wm[c,d] (+ bias[d])
// Block tile: 96 d x 128 px, K chunked by 48. 192 threads = 6 warps
// (3 d-way x 2 px-way); warp tile 32d x 64px (lane = 4 ld x 8 lp);
// thread tile 8d x 8px (32 FMA2, 4 LDS.128, ~6 wavefronts per warp-step).
// 42KB smem -> 3 blocks/SM (18 warps), cross-block phase overlap.
// ============================================================================
__global__ void __launch_bounds__(192, 3) gemm192_kernel(
    const float* __restrict__ X, const float* __restrict__ Wm,
    const float* __restrict__ bias, float* __restrict__ Out)
{
    __shared__ float xs[48][128];
    __shared__ float ws[48][96];
    const int tid  = threadIdx.x;
    const int b    = blockIdx.x;
    const int pt   = b >> 1;               // 392 pixel tiles
    const int dt   = b & 1;                // 2 d tiles
    const int g0   = pt * 128;
    const int dbase= dt * 96;
    const int warp = tid >> 5, lane = tid & 31;
    const int wd   = warp % 3, wp = warp / 3;
    const int ld   = lane >> 3, lp = lane & 7;
    const int d0   = wd*32 + ld*8;         // block-local d
    const int p0   = wp*64 + lp*8;         // block-local px

    unsigned long long acc[8][4];
    #pragma unroll
    for (int di = 0; di < 8; di++) {
        float bb = bias ? bias[dbase + d0 + di] : 0.0f;
        unsigned long long b2 = pack2(bb, bb);
        #pragma unroll
        for (int pp = 0; pp < 4; pp++) acc[di][pp] = b2;
    }

    for (int kc = 0; kc < 4; kc++) {
        __syncthreads();
        // xs: 48 rows x 128 px = 1536 float4, 8 per thread
        #pragma unroll
        for (int s = 0; s < 8; s++) {
            int idx = tid + s*192;
            int k = idx >> 5, p4 = idx & 31;
            int g = g0 + p4*4;
            int n = g / HWP, hw = g - n*HWP;
            *(float4*)&xs[k][p4*4] =
                *(const float4*)&X[((size_t)(n*CC) + kc*48 + k)*HWP + hw];
        }
        // ws: 48 rows x 96 d = 1152 float4, 6 per thread
        #pragma unroll
        for (int s = 0; s < 6; s++) {
            int idx = tid + s*192;
            int k = idx / 24, c4 = idx - k*24;
            *(float4*)&ws[k][c4*4] =
                *(const float4*)&Wm[(size_t)(kc*48 + k)*192 + dbase + c4*4];
        }
        __syncthreads();

        #pragma unroll 4
        for (int r = 0; r < 48; r++) {
            float4 wa = *(const float4*)&ws[r][d0];
            float4 wb = *(const float4*)&ws[r][d0+4];
            ulonglong2 xv0 = *(const ulonglong2*)&xs[r][p0];
            ulonglong2 xv1 = *(const ulonglong2*)&xs[r][p0+4];
            unsigned long long xp[4] = {xv0.x, xv0.y, xv1.x, xv1.y};
            unsigned long long w2[8];
            w2[0]=pack2(wa.x,wa.x); w2[1]=pack2(wa.y,wa.y);
            w2[2]=pack2(wa.z,wa.z); w2[3]=pack2(wa.w,wa.w);
            w2[4]=pack2(wb.x,wb.x); w2[5]=pack2(wb.y,wb.y);
            w2[6]=pack2(wb.z,wb.z); w2[7]=pack2(wb.w,wb.w);
            #pragma unroll
            for (int di = 0; di < 8; di++)
                #pragma unroll
                for (int pp = 0; pp < 4; pp++)
                    FMA2(acc[di][pp], xp[pp], w2[di]);
        }
    }

    // epilogue: 2 float4 per d-row
    #pragma unroll
    for (int s = 0; s < 2; s++) {
        int g = g0 + p0 + s*4;
        int n = g / HWP, hw = g - n*HWP;
        #pragma unroll
        for (int di = 0; di < 8; di++) {
            ulonglong2 uv; uv.x = acc[di][2*s]; uv.y = acc[di][2*s+1];
            *(ulonglong2*)&Out[((size_t)(n*CC) + dbase + d0 + di)*HWP + hw] = uv;
        }
    }
}

// ============================================================================
// Kernel B: attention logits GEMM + fused register softmax.
// Block tile: 486 cols x 64 px, K chunked by 32. 432 threads: cg=tid>>3
// (54 groups of 9 cols = one softmax group), pg=tid&7 (8 px each).
// Warp = 4 cg x 8 pg: w = 3 aligned LDS.128 (padded-12 layout), x = 2 LDS.128,
// 36 FMA2 per step. Output to padded [px][54][12] layout, 3 STG.128/px.
// ============================================================================
#define ATT_SMEM_BYTES ((32*64 + 32*KTP)*4)      // 91136

__global__ void __launch_bounds__(432, 1) att_kernel(
    const float* __restrict__ X, const float* __restrict__ Wpad,
    const float* __restrict__ ba, float* __restrict__ Att)
{
    extern __shared__ float sm[];
    float* xs = sm;                 // [32][64]
    float* ws = sm + 32*64;         // [32][648]
    const int tid = threadIdx.x;
    const int cg  = tid >> 3;       // 0..53
    const int pg  = tid & 7;        // 0..7
    const int bb  = blockIdx.x;
    const int n   = bb / 49;
    const int hw0 = (bb - n*49) * 64;

    unsigned long long acc[9][4];
    #pragma unroll
    for (int u = 0; u < 9; u++) {
        float bv = ba[9*cg + u];
        unsigned long long b2 = pack2(bv, bv);
        #pragma unroll
        for (int pp = 0; pp < 4; pp++) acc[u][pp] = b2;
    }

    for (int kc = 0; kc < 6; kc++) {
        __syncthreads();
        // xs: 32x64 = 512 float4
        for (int idx = tid; idx < 512; idx += 432) {
            int k = idx >> 4, p4 = idx & 15;
            *(float4*)&xs[k*64 + p4*4] =
                *(const float4*)&X[((size_t)(n*CC) + kc*32 + k)*HWP + hw0 + p4*4];
        }
        // ws: 32x648 = 5184 float4
        for (int idx = tid; idx < 5184; idx += 432) {
            int k = idx / 162, c4 = idx - k*162;
            *(float4*)&ws[k*KTP + c4*4] =
                *(const float4*)&Wpad[(size_t)(kc*32 + k)*KTP + c4*4];
        }
        __syncthreads();

        #pragma unroll 2
        for (int r = 0; r < 32; r++) {
            float4 q0 = *(const float4*)&ws[r*KTP + 12*cg];
            float4 q1 = *(const float4*)&ws[r*KTP + 12*cg + 4];
            float  q8 = ws[r*KTP + 12*cg + 8];
            ulonglong2 xv0 = *(const ulonglong2*)&xs[r*64 + 8*pg];
            ulonglong2 xv1 = *(const ulonglong2*)&xs[r*64 + 8*pg + 4];
            unsigned long long xp[4] = {xv0.x, xv0.y, xv1.x, xv1.y};
            unsigned long long w2[9];
            w2[0]=pack2(q0.x,q0.x); w2[1]=pack2(q0.y,q0.y); w2[2]=pack2(q0.z,q0.z);
            w2[3]=pack2(q0.w,q0.w); w2[4]=pack2(q1.x,q1.x); w2[5]=pack2(q1.y,q1.y);
            w2[6]=pack2(q1.z,q1.z); w2[7]=pack2(q1.w,q1.w); w2[8]=pack2(q8,q8);
            #pragma unroll
            for (int u = 0; u < 9; u++)
                #pragma unroll
                for (int pp = 0; pp < 4; pp++)
                    FMA2(acc[u][pp], xp[pp], w2[u]);
        }
    }

    // register softmax over the 9 cols per pixel; padded stores
    #pragma unroll
    for (int pp = 0; pp < 4; pp++) {
        float z0[9], z1[9];
        #pragma unroll
        for (int u = 0; u < 9; u++) unpack2(acc[u][pp], z0[u], z1[u]);
        #pragma unroll
        for (int half = 0; half < 2; half++) {
            float* z = half ? z1 : z0;
            float m = z[0];
            #pragma unroll
            for (int u = 1; u < 9; u++) m = fmaxf(m, z[u]);
            float e[9], s = 0.0f;
            #pragma unroll
            for (int u = 0; u < 9; u++) { e[u] = __expf((z[u]-m)*SCALE); s += e[u]; }
            float inv = 1.0f / s;
            int px = 8*pg + 2*pp + half;
            float* dst = Att + ((size_t)(n*HWP) + hw0 + px)*KTP + cg*12;
            float4 f0 = {e[0]*inv, e[1]*inv, e[2]*inv, e[3]*inv};
            float4 f1 = {e[4]*inv, e[5]*inv, e[6]*inv, e[7]*inv};
            float4 f2 = {e[8]*inv, 0.0f, 0.0f, 0.0f};
            *(float4*)(dst)     = f0;
            *(float4*)(dst + 4) = f1;
            *(float4*)(dst + 8) = f2;
        }
    }
}

// ============================================================================
// Kernel C: aggregation + fold (gather formulation, race-free).
// 384 threads = 6 heads x 64 pixels (8x8 tile); 81 att weights loaded once
// per thread (27 aligned LDG.128 from padded layout), reused over 32 channels.
// ============================================================================
#define AGG_SMEM_BYTES ((192*145 + 192*64)*4)    // 160512

__global__ void __launch_bounds__(384, 1) agg_kernel(
    const float* __restrict__ V, const float* __restrict__ Att,
    float* __restrict__ Fold)
{
    extern __shared__ float sm[];
    float* vsm = sm;               // [192][145]
    float* fsm = sm + 192*145;     // [192][64]
    const int tid = threadIdx.x;
    const int blk = blockIdx.x;
    const int n  = blk / 49;
    const int tt = blk - n*49;
    const int y0 = (tt / 7) * 8, x0 = (tt % 7) * 8;

    for (int i = tid; i < 192*144; i += 384) {
        int c = i / 144, pos = i - c*144;
        int ly = pos / 12, lx = pos - ly*12;
        int gy = y0 - 2 + ly, gx = x0 - 2 + lx;
        float val = 0.0f;
        if (gy >= 0 && gy < HH && gx >= 0 && gx < WW)
            val = V[((size_t)(n*CC) + c)*HWP + gy*WW + gx];
        vsm[c*145 + pos] = val;
    }
    __syncthreads();

    {
        const int head = tid >> 6;          // 0..5
        const int q    = tid & 63;
        const int qy = q >> 3, qx = q & 7;
        const int gy = y0 + qy, gx = x0 + qx;

        float w[81];
        #pragma unroll
        for (int i = 0; i < 3; i++)
        #pragma unroll
        for (int j = 0; j < 3; j++) {
            int py = gy + 1 - i, px = gx + 1 - j;
            int kk = i*3 + j;
            if (py >= 0 && py < HH && px >= 0 && px < WW) {
                const float* ab = Att + ((size_t)n*HWP + py*WW + px)*KTP
                                      + head*108 + kk*12;
                float4 a0 = *(const float4*)(ab);
                float4 a1 = *(const float4*)(ab + 4);
                float  a8 = ab[8];
                w[kk*9+0]=a0.x; w[kk*9+1]=a0.y; w[kk*9+2]=a0.z; w[kk*9+3]=a0.w;
                w[kk*9+4]=a1.x; w[kk*9+5]=a1.y; w[kk*9+6]=a1.z; w[kk*9+7]=a1.w;
                w[kk*9+8]=a8;
            } else {
                #pragma unroll
                for (int u = 0; u < 9; u++) w[kk*9+u] = 0.0f;
            }
        }

        #pragma unroll 1
        for (int ch = 0; ch < CHN; ch++) {
            const int cg = head*CHN + ch;
            const float* vb = vsm + cg*145;
            float vv[25];
            #pragma unroll
            for (int dy = 0; dy < 5; dy++)
            #pragma unroll
            for (int dx = 0; dx < 5; dx++)
                vv[dy*5+dx] = vb[(qy+dy)*12 + (qx+dx)];

            float p0=0.f, p1=0.f, p2=0.f, p3=0.f;
            #pragma unroll
            for (int i = 0; i < 3; i++)
            #pragma unroll
            for (int j = 0; j < 3; j++)
            #pragma unroll
            for (int a = 0; a < 3; a++)
            #pragma unroll
            for (int bb = 0; bb < 3; bb++) {
                const int widx = (i*3+j)*9 + a*3 + bb;
                float prod = w[widx] * vv[(a-i+2)*5 + (bb-j+2)];
                switch (widx & 3) { case 0: p0 += prod; break; case 1: p1 += prod; break;
                                    case 2: p2 += prod; break; default: p3 += prod; }
            }
            fsm[cg*64 + q] = (p0+p1) + (p2+p3);
        }
    }
    __syncthreads();

    for (int i = tid; i < 192*64; i += 384) {
        int c = i >> 6, q = i & 63;
        int qy = q >> 3, qx = q & 7;
        Fold[((size_t)(n*CC) + c)*HWP + (y0+qy)*WW + (x0+qx)] = fsm[i];
    }
}

// ============================================================================
// Launch
// ============================================================================
extern "C" void kernel_launch(void* const* d_in, const int* in_sizes, int n_in,
                              void* d_out, int out_size)
{
    const float* x  = (const float*)d_in[0];
    const float* Wv = (const float*)d_in[1];
    const float* Wa = (const float*)d_in[2];
    const float* ba = (const float*)d_in[3];
    const float* Wp = (const float*)d_in[4];
    const float* bp = (const float*)d_in[5];
    float* out = (float*)d_out;

    float *vp, *ap, *fp, *wpad;
    cudaGetSymbolAddress((void**)&vp, g_v);
    cudaGetSymbolAddress((void**)&ap, g_att);
    cudaGetSymbolAddress((void**)&fp, g_fold);
    cudaGetSymbolAddress((void**)&wpad, g_wpad);

    cudaFuncSetAttribute(att_kernel, cudaFuncAttributeMaxDynamicSharedMemorySize, ATT_SMEM_BYTES);
    cudaFuncSetAttribute(agg_kernel, cudaFuncAttributeMaxDynamicSharedMemorySize, AGG_SMEM_BYTES);

    // pad Wa -> [192][648]
    pad_wa_kernel<<<(CC*KTP + 255)/256, 256>>>(Wa, wpad);
    // value projection: v = x @ Wv
    gemm192_kernel<<<392*2, 192>>>(x, Wv, nullptr, vp);
    // attention logits + fused softmax (padded output)
    att_kernel<<<NB*49, 432, ATT_SMEM_BYTES>>>(x, wpad, ba, ap);
    // aggregation + fold
    agg_kernel<<<NB*49, 384, AGG_SMEM_BYTES>>>(vp, ap, fp);
    // output projection: out = folded @ Wp + bp
    gemm192_kernel<<<392*2, 192>>>(fp, Wp, bp, out);
}

// round 4
// speedup vs baseline: 1.7689x; 1.0680x over previous
#include <cuda_runtime.h>
#include <cstdint>
#include <cstddef>

#define NB    16
#define CC    192
#define HH    56
#define WW    56
#define HWP   (HH*WW)          // 3136
#define NPIX  (NB*HWP)         // 50176
#define HEADS 6
#define CHN   32
#define KT    486              // 81 * 6
#define KTP   648              // padded: 54 groups * 12
#define SCALE 0.17677669529663689f   // 32^-0.5

// ---------------- scratch (device globals; no runtime allocation) -------------
__device__ float g_v   [NB*CC*HWP];                 // value projection    (38.5 MB)
__device__ float g_att [(size_t)NPIX*KTP];          // softmaxed att, padded (130 MB)
__device__ float g_fold[NB*CC*HWP];                 // folded result       (38.5 MB)
__device__ float g_wpad[CC*KTP];                    // padded Wa           (497 KB)

// ---------------- packed f32x2 helpers ---------------------------------------
#define FMA2(acc,a,b) asm("fma.rn.f32x2 %0, %1, %2, %0;" : "+l"(acc) : "l"(a), "l"(b))

__device__ __forceinline__ unsigned long long pack2(float x, float y) {
    unsigned long long r;
    asm("mov.b64 %0, {%1, %2};" : "=l"(r) : "r"(__float_as_uint(x)), "r"(__float_as_uint(y)));
    return r;
}
__device__ __forceinline__ void unpack2(unsigned long long v, float& x, float& y) {
    unsigned int lo, hi;
    asm("mov.b64 {%0, %1}, %2;" : "=r"(lo), "=r"(hi) : "l"(v));
    x = __uint_as_float(lo); y = __uint_as_float(hi);
}

// ============================================================================
// Wa pre-pad: [192][486] -> [192][648], group g's 9 cols at 12g..12g+8, pad 0.
// ============================================================================
__global__ void pad_wa_kernel(const float* __restrict__ Wa, float* __restrict__ Wp)
{
    int i = blockIdx.x * 256 + threadIdx.x;
    if (i >= CC*KTP) return;
    int c = i / KTP, col = i - c*KTP;
    int g = col / 12, u = col - g*12;
    Wp[i] = (u < 9) ? Wa[c*KT + g*9 + u] : 0.0f;
}

// ============================================================================
// Kernel A/D: 192x192 pointwise GEMM, SIMT outer-product tiling. (unchanged)
// ============================================================================
__global__ void __launch_bounds__(192, 3) gemm192_kernel(
    const float* __restrict__ X, const float* __restrict__ Wm,
    const float* __restrict__ bias, float* __restrict__ Out)
{
    __shared__ float xs[48][128];
    __shared__ float ws[48][96];
    const int tid  = threadIdx.x;
    const int b    = blockIdx.x;
    const int pt   = b >> 1;
    const int dt   = b & 1;
    const int g0   = pt * 128;
    const int dbase= dt * 96;
    const int warp = tid >> 5, lane = tid & 31;
    const int wd   = warp % 3, wp = warp / 3;
    const int ld   = lane >> 3, lp = lane & 7;
    const int d0   = wd*32 + ld*8;
    const int p0   = wp*64 + lp*8;

    unsigned long long acc[8][4];
    #pragma unroll
    for (int di = 0; di < 8; di++) {
        float bb = bias ? bias[dbase + d0 + di] : 0.0f;
        unsigned long long b2 = pack2(bb, bb);
        #pragma unroll
        for (int pp = 0; pp < 4; pp++) acc[di][pp] = b2;
    }

    for (int kc = 0; kc < 4; kc++) {
        __syncthreads();
        #pragma unroll
        for (int s = 0; s < 8; s++) {
            int idx = tid + s*192;
            int k = idx >> 5, p4 = idx & 31;
            int g = g0 + p4*4;
            int n = g / HWP, hw = g - n*HWP;
            *(float4*)&xs[k][p4*4] =
                *(const float4*)&X[((size_t)(n*CC) + kc*48 + k)*HWP + hw];
        }
        #pragma unroll
        for (int s = 0; s < 6; s++) {
            int idx = tid + s*192;
            int k = idx / 24, c4 = idx - k*24;
            *(float4*)&ws[k][c4*4] =
                *(const float4*)&Wm[(size_t)(kc*48 + k)*192 + dbase + c4*4];
        }
        __syncthreads();

        #pragma unroll 4
        for (int r = 0; r < 48; r++) {
            float4 wa = *(const float4*)&ws[r][d0];
            float4 wb = *(const float4*)&ws[r][d0+4];
            ulonglong2 xv0 = *(const ulonglong2*)&xs[r][p0];
            ulonglong2 xv1 = *(const ulonglong2*)&xs[r][p0+4];
            unsigned long long xp[4] = {xv0.x, xv0.y, xv1.x, xv1.y};
            unsigned long long w2[8];
            w2[0]=pack2(wa.x,wa.x); w2[1]=pack2(wa.y,wa.y);
            w2[2]=pack2(wa.z,wa.z); w2[3]=pack2(wa.w,wa.w);
            w2[4]=pack2(wb.x,wb.x); w2[5]=pack2(wb.y,wb.y);
            w2[6]=pack2(wb.z,wb.z); w2[7]=pack2(wb.w,wb.w);
            #pragma unroll
            for (int di = 0; di < 8; di++)
                #pragma unroll
                for (int pp = 0; pp < 4; pp++)
                    FMA2(acc[di][pp], xp[pp], w2[di]);
        }
    }

    #pragma unroll
    for (int s = 0; s < 2; s++) {
        int g = g0 + p0 + s*4;
        int n = g / HWP, hw = g - n*HWP;
        #pragma unroll
        for (int di = 0; di < 8; di++) {
            ulonglong2 uv; uv.x = acc[di][2*s]; uv.y = acc[di][2*s+1];
            *(ulonglong2*)&Out[((size_t)(n*CC) + dbase + d0 + di)*HWP + hw] = uv;
        }
    }
}

// ============================================================================
// Kernel B: attention logits GEMM + fused register softmax.
// 864 threads: cg = tid>>4 (54 groups of 9 cols), pg = tid&15 (4 px each).
// Thread tile: 9 cols x 4 px = 18 ull accs (36 regs) -> no spills at the
// 75-reg cap, 27 warps/SM. Block tile: 486 cols x 64 px, K chunked by 32.
// ============================================================================
#define ATT_SMEM_BYTES ((32*64 + 32*KTP)*4)      // 91136

__global__ void __launch_bounds__(864, 1) att_kernel(
    const float* __restrict__ X, const float* __restrict__ Wpad,
    const float* __restrict__ ba, float* __restrict__ Att)
{
    extern __shared__ float sm[];
    float* xs = sm;                 // [32][64]
    float* ws = sm + 32*64;         // [32][648]
    const int tid = threadIdx.x;
    const int cg  = tid >> 4;       // 0..53
    const int pg  = tid & 15;       // 0..15 -> px [4pg, 4pg+4)
    const int bb  = blockIdx.x;
    const int n   = bb / 49;
    const int hw0 = (bb - n*49) * 64;

    unsigned long long acc[9][2];
    #pragma unroll
    for (int u = 0; u < 9; u++) {
        float bv = ba[9*cg + u];
        unsigned long long b2 = pack2(bv, bv);
        acc[u][0] = b2; acc[u][1] = b2;
    }

    for (int kc = 0; kc < 6; kc++) {
        __syncthreads();
        if (tid < 512) {
            int k = tid >> 4, p4 = tid & 15;
            *(float4*)&xs[k*64 + p4*4] =
                *(const float4*)&X[((size_t)(n*CC) + kc*32 + k)*HWP + hw0 + p4*4];
        }
        #pragma unroll
        for (int s = 0; s < 6; s++) {
            int idx = tid + s*864;
            int k = idx / 162, c4 = idx - k*162;
            *(float4*)&ws[k*KTP + c4*4] =
                *(const float4*)&Wpad[(size_t)(kc*32 + k)*KTP + c4*4];
        }
        __syncthreads();

        #pragma unroll 2
        for (int r = 0; r < 32; r++) {
            float4 q0 = *(const float4*)&ws[r*KTP + 12*cg];
            float4 q1 = *(const float4*)&ws[r*KTP + 12*cg + 4];
            float  q8 = ws[r*KTP + 12*cg + 8];
            ulonglong2 xv = *(const ulonglong2*)&xs[r*64 + 4*pg];
            unsigned long long xp0 = xv.x, xp1 = xv.y;
            float wv[9] = {q0.x,q0.y,q0.z,q0.w,q1.x,q1.y,q1.z,q1.w,q8};
            #pragma unroll
            for (int u = 0; u < 9; u++) {
                unsigned long long w2 = pack2(wv[u], wv[u]);
                FMA2(acc[u][0], xp0, w2);
                FMA2(acc[u][1], xp1, w2);
            }
        }
    }

    // register softmax over the 9 cols per pixel; padded stores
    #pragma unroll
    for (int pp = 0; pp < 2; pp++) {
        float z0[9], z1[9];
        #pragma unroll
        for (int u = 0; u < 9; u++) unpack2(acc[u][pp], z0[u], z1[u]);
        #pragma unroll
        for (int half = 0; half < 2; half++) {
            float* z = half ? z1 : z0;
            float m = z[0];
            #pragma unroll
            for (int u = 1; u < 9; u++) m = fmaxf(m, z[u]);
            float e[9], s = 0.0f;
            #pragma unroll
            for (int u = 0; u < 9; u++) { e[u] = __expf((z[u]-m)*SCALE); s += e[u]; }
            float inv = 1.0f / s;
            int px = 4*pg + 2*pp + half;
            float* dst = Att + ((size_t)(n*HWP) + hw0 + px)*KTP + cg*12;
            float4 f0 = {e[0]*inv, e[1]*inv, e[2]*inv, e[3]*inv};
            float4 f1 = {e[4]*inv, e[5]*inv, e[6]*inv, e[7]*inv};
            float4 f2 = {e[8]*inv, 0.0f, 0.0f, 0.0f};
            *(float4*)(dst)     = f0;
            *(float4*)(dst + 4) = f1;
            *(float4*)(dst + 8) = f2;
        }
    }
}

// ============================================================================
// Kernel C: aggregation + fold, 5x5 collapsed stencil.
// Because attention weights are channel-independent, the 81-term sum per
// channel collapses: W2[dy][dx] = sum_{a-i=dy-2, b-j=dx-2} w[ij][ab]
// (built once per (head,pixel)), then each channel-PAIR needs only
// 25 FMA2 + 25 LDS.64. v stored as ulonglong [chpair][145] (odd 8B stride
// -> the (qy,qx) lane pattern gives conflict-free LDS.64).
// ============================================================================
#define AGG_SMEM_BYTES (96*145*8 + 192*64*4)     // 160512

__global__ void __launch_bounds__(384, 1) agg_kernel(
    const float* __restrict__ V, const float* __restrict__ Att,
    float* __restrict__ Fold)
{
    extern __shared__ char smraw[];
    unsigned long long* vsm2 = (unsigned long long*)smraw;      // [96][145]
    float* fsm = (float*)(smraw + 96*145*8);                    // [192][64]
    const int tid = threadIdx.x;
    const int blk = blockIdx.x;
    const int n  = blk / 49;
    const int tt = blk - n*49;
    const int y0 = (tt / 7) * 8, x0 = (tt % 7) * 8;

    // load v window as channel pairs
    for (int i = tid; i < 96*144; i += 384) {
        int cp = i / 144, pos = i - cp*144;
        int ly = pos / 12, lx = pos - ly*12;
        int gy = y0 - 2 + ly, gx = x0 - 2 + lx;
        float a = 0.0f, b = 0.0f;
        if (gy >= 0 && gy < HH && gx >= 0 && gx < WW) {
            const float* vb = &V[((size_t)(n*CC) + 2*cp)*HWP + gy*WW + gx];
            a = vb[0]; b = vb[HWP];
        }
        vsm2[cp*145 + pos] = pack2(a, b);
    }
    __syncthreads();

    {
        const int head = tid >> 6;          // 0..5
        const int q    = tid & 63;
        const int qy = q >> 3, qx = q & 7;
        const int gy = y0 + qy, gx = x0 + qx;

        // build collapsed 5x5 stencil from up to 9 neighbor att rows
        float W2[25];
        #pragma unroll
        for (int p = 0; p < 25; p++) W2[p] = 0.0f;
        #pragma unroll
        for (int i = 0; i < 3; i++)
        #pragma unroll
        for (int j = 0; j < 3; j++) {
            int py = gy + 1 - i, px = gx + 1 - j;
            if (py >= 0 && py < HH && px >= 0 && px < WW) {
                const float* ab = Att + ((size_t)n*HWP + py*WW + px)*KTP
                                      + head*108 + (i*3+j)*12;
                float4 a0 = *(const float4*)(ab);
                float4 a1 = *(const float4*)(ab + 4);
                float  a8 = ab[8];
                float av[9] = {a0.x,a0.y,a0.z,a0.w,a1.x,a1.y,a1.z,a1.w,a8};
                #pragma unroll
                for (int a = 0; a < 3; a++)
                #pragma unroll
                for (int b = 0; b < 3; b++)
                    W2[(a-i+2)*5 + (b-j+2)] += av[a*3+b];
            }
        }
        unsigned long long w22[25];
        #pragma unroll
        for (int p = 0; p < 25; p++) w22[p] = pack2(W2[p], W2[p]);

        const int pos0 = qy*12 + qx;
        #pragma unroll 2
        for (int cp16 = 0; cp16 < 16; cp16++) {
            const int cp = head*16 + cp16;
            const unsigned long long* vb = vsm2 + cp*145 + pos0;
            unsigned long long acA = 0ull, acB = 0ull;
            #pragma unroll
            for (int p = 0; p < 25; p++) {
                const int off = (p/5)*12 + (p%5);
                if (p & 1) { FMA2(acB, vb[off], w22[p]); }
                else       { FMA2(acA, vb[off], w22[p]); }
            }
            float xa, ya, xb, yb;
            unpack2(acA, xa, ya); unpack2(acB, xb, yb);
            fsm[(2*cp  )*64 + q] = xa + xb;
            fsm[(2*cp+1)*64 + q] = ya + yb;
        }
    }
    __syncthreads();

    for (int i = tid; i < 192*64; i += 384) {
        int c = i >> 6, q = i & 63;
        int qy = q >> 3, qx = q & 7;
        Fold[((size_t)(n*CC) + c)*HWP + (y0+qy)*WW + (x0+qx)] = fsm[i];
    }
}

// ============================================================================
// Launch
// ============================================================================
extern "C" void kernel_launch(void* const* d_in, const int* in_sizes, int n_in,
                              void* d_out, int out_size)
{
    const float* x  = (const float*)d_in[0];
    const float* Wv = (const float*)d_in[1];
    const float* Wa = (const float*)d_in[2];
    const float* ba = (const float*)d_in[3];
    const float* Wp = (const float*)d_in[4];
    const float* bp = (const float*)d_in[5];
    float* out = (float*)d_out;

    float *vp, *ap, *fp, *wpad;
    cudaGetSymbolAddress((void**)&vp, g_v);
    cudaGetSymbolAddress((void**)&ap, g_att);
    cudaGetSymbolAddress((void**)&fp, g_fold);
    cudaGetSymbolAddress((void**)&wpad, g_wpad);

    cudaFuncSetAttribute(att_kernel, cudaFuncAttributeMaxDynamicSharedMemorySize, ATT_SMEM_BYTES);
    cudaFuncSetAttribute(agg_kernel, cudaFuncAttributeMaxDynamicSharedMemorySize, AGG_SMEM_BYTES);

    // pad Wa -> [192][648]
    pad_wa_kernel<<<(CC*KTP + 255)/256, 256>>>(Wa, wpad);
    // value projection: v = x @ Wv
    gemm192_kernel<<<392*2, 192>>>(x, Wv, nullptr, vp);
    // attention logits + fused softmax (padded output)
    att_kernel<<<NB*49, 864, ATT_SMEM_BYTES>>>(x, wpad, ba, ap);
    // aggregation + fold (collapsed 5x5 stencil)
    agg_kernel<<<NB*49, 384, AGG_SMEM_BYTES>>>(vp, ap, fp);
    // output projection: out = folded @ Wp + bp
    gemm192_kernel<<<392*2, 192>>>(fp, Wp, bp, out);
}